// round 17
// baseline (speedup 1.0000x reference)
#include <cuda_runtime.h>
#include <math.h>
#include <stdint.h>

// Problem constants (match reference setup_inputs)
#define DIMF     2048
#define KIDS     8
#define P        256
#define HALF     2048
#define MARGIN   1.0f

#define GRID     296                  // exactly 2 CTAs per SM (148 SMs)
#define THREADS  256
#define GROUP    16                   // rows per identity (2*K)
#define NTASK    1024                 // 256 identities x 4 K-quarters
#define CHUNK    512                  // K floats per task (one quarter)
#define STRIDE_F 516                  // padded smem row stride (floats)
#define ROW_BYTES    (CHUNK * 4)      // 2048 B per row per task
#define STRIDE_BYTES (STRIDE_F * 4)   // 2064 (16B multiple)
#define BUF_FLOATS   (GROUP * STRIDE_F)
#define BUF_BYTES    (GROUP * STRIDE_BYTES)   // 33024
#define SMEM_BYTES   (2 * BUF_BYTES)          // 66048 (double buffer)

// D(16x8) += A(16x8) * B(8x8), tf32. Gram trick: B fragments are A fragments.
#define MMA_TF32(d, a0, a1, a2, a3, b0, b1)                                \
    asm volatile(                                                          \
        "mma.sync.aligned.m16n8k8.row.col.f32.tf32.tf32.f32 "              \
        "{%0,%1,%2,%3}, {%4,%5,%6,%7}, {%8,%9}, {%0,%1,%2,%3};"            \
        : "+f"(d[0]), "+f"(d[1]), "+f"(d[2]), "+f"(d[3])                   \
        : "r"(a0), "r"(a1), "r"(a2), "r"(a3), "r"(b0), "r"(b1))

__device__ float g_gram[P][GROUP * GROUP];   // zero-init; self-resetting
__device__ int   g_done[P];                  // zero-init; self-resetting

__device__ __forceinline__ uint32_t smem_u32(const void* p) {
    return (uint32_t)__cvta_generic_to_shared(p);
}
__device__ __forceinline__ void mbar_wait(uint32_t mbar, uint32_t parity) {
    asm volatile(
        "{\n\t.reg .pred P1;\n\t"
        "LAB_WAIT_%=:\n\t"
        "mbarrier.try_wait.parity.acquire.cta.shared::cta.b64 P1, [%0], %1, 0x989680;\n\t"
        "@P1 bra.uni LAB_DONE_%=;\n\t"
        "bra.uni LAB_WAIT_%=;\n\t"
        "LAB_DONE_%=:\n\t}"
        :: "r"(mbar), "r"(parity) : "memory");
}
// task -> CTA mapping: c(t) = (t*296)>>10 ; CTA c owns a contiguous range.
__device__ __forceinline__ int task_lo(int c)  { return (c * NTASK + GRID - 1) / GRID; }
__device__ __forceinline__ int cover_of(int id) {
    return ((4 * id + 3) * GRID >> 10) - ((4 * id) * GRID >> 10) + 1;
}

__global__ __launch_bounds__(THREADS, 2)
void wloss_kernel(const float* __restrict__ x, float* __restrict__ out)
{
    extern __shared__ float smf[];               // [2][16][STRIDE_F]
    __shared__ uint64_t s_mbar[2];
    __shared__ int      s_win;

    const int tid  = threadIdx.x;
    const int w    = tid >> 5;                   // warp 0..7 (k split)
    const int lane = tid & 31;
    const int c    = blockIdx.x;

    const int t_lo = task_lo(c);
    const int t_hi = task_lo(c + 1) - 1;
    const int n    = t_hi - t_lo + 1;            // 3 or 4 tasks

    const uint32_t smbase = smem_u32(smf);
    const uint32_t mbb    = smem_u32(&s_mbar[0]);

    if (tid == 0) {
        asm volatile("mbarrier.init.shared.b64 [%0], 1;" :: "r"(mbb)      : "memory");
        asm volatile("mbarrier.init.shared.b64 [%0], 1;" :: "r"(mbb + 8u) : "memory");
    }
    __syncthreads();

    // ---- bulk-async staging of task t into buffer b ----
    auto stage = [&](int t, int b) {
        int id = t >> 2, kq = t & 3;
        uint32_t mb = mbb + 8u * b;
        asm volatile("mbarrier.arrive.expect_tx.shared.b64 _, [%0], %1;"
                     :: "r"(mb), "r"((uint32_t)(GROUP * ROW_BYTES)) : "memory");
        #pragma unroll
        for (int r = 0; r < GROUP; r++) {
            int grow = (r < KIDS) ? (id * KIDS + r)
                                  : (HALF + id * KIDS + (r - KIDS));
            const float* src = x + (size_t)grow * DIMF + kq * CHUNK;
            uint32_t dst = smbase + (uint32_t)(b * BUF_BYTES + r * STRIDE_BYTES);
            asm volatile(
                "cp.async.bulk.shared::cluster.global.mbarrier::complete_tx::bytes "
                "[%0], [%1], %2, [%3];"
                :: "r"(dst), "l"(src), "r"((uint32_t)ROW_BYTES), "r"(mb)
                : "memory");
        }
    };

    if (tid == 0) {
        stage(t_lo, 0);
        if (n > 1) stage(t_lo + 1, 1);
    }

    const int fr = lane >> 2;                    // fragment row 0..7
    const int ft = lane & 3;                     // fragment k 0..3
    float d1[4] = {0.f, 0.f, 0.f, 0.f};          // cols 0..7
    float d2[4] = {0.f, 0.f, 0.f, 0.f};          // cols 8..15

    const int rr = lane >> 2;
    const int cc = 2 * (lane & 3);

    // flush identity partial to global gram; elect last CTA; loss if winner
    auto flush_identity = [&](int id) {
        float* g = &g_gram[id][0];
        atomicAdd(&g[rr * 16 + cc],            d1[0]);
        atomicAdd(&g[rr * 16 + cc + 1],        d1[1]);
        atomicAdd(&g[(rr + 8) * 16 + cc],      d1[2]);
        atomicAdd(&g[(rr + 8) * 16 + cc + 1],  d1[3]);
        atomicAdd(&g[rr * 16 + 8 + cc],        d2[0]);
        atomicAdd(&g[rr * 16 + 8 + cc + 1],    d2[1]);
        atomicAdd(&g[(rr + 8) * 16 + 8 + cc],  d2[2]);
        atomicAdd(&g[(rr + 8) * 16 + 8 + cc + 1], d2[3]);
        #pragma unroll
        for (int i = 0; i < 4; i++) { d1[i] = 0.f; d2[i] = 0.f; }
        __threadfence();
        __syncthreads();                          // all REDG issued+fenced
        if (tid == 0) {
            int v = atomicAdd(&g_done[id], 1);
            s_win = (v == cover_of(id) - 1);
        }
        __syncthreads();
        if (s_win && w == 0) {
            __threadfence();
            // lane r (r<16) loads row r of the merged gram
            float row[GROUP];
            const int r = lane & 15;
            #pragma unroll
            for (int cI = 0; cI < GROUP; cI++)
                row[cI] = __ldcg(&g_gram[id][r * GROUP + cI]);
            float inv = 1.0f / (sqrtf(row[r]) + 1e-10f);
            float minf = INFINITY, mins = INFINITY;
            #pragma unroll
            for (int cI = 0; cI < GROUP; cI++) {
                float invc = __shfl_sync(0xffffffffu, inv, cI);
                float v2 = row[cI] * inv * invc;
                if (cI < KIDS) minf = fminf(minf, v2);
                else           mins = fminf(mins, v2);
            }
            float li = fmaxf(MARGIN - minf, 0.0f) + fmaxf(MARGIN - mins, 0.0f);
            if (lane >= 16) li = 0.0f;
            #pragma unroll
            for (int o = 16; o; o >>= 1)
                li += __shfl_xor_sync(0xffffffffu, li, o);
            if (lane == 0) {
                atomicAdd(out, li);
                g_done[id] = 0;                   // reset for next replay
            }
            // reset gram (32 lanes x 8 values)
            #pragma unroll
            for (int j = 0; j < 8; j++)
                g_gram[id][lane * 8 + j] = 0.0f;
            __threadfence();
        }
    };

    // ---- main loop over this CTA's contiguous tasks ----
    int cur_id = t_lo >> 2;
    for (int i = 0; i < n; i++) {
        const int t = t_lo + i;
        const int b = i & 1;
        mbar_wait(mbb + 8u * b, (uint32_t)((i >> 1) & 1));

        const int id_t = t >> 2;
        if (id_t != cur_id) {                     // identity boundary
            flush_identity(cur_id);
            cur_id = id_t;
        }

        const float* b0p = smf + b * BUF_FLOATS + fr * STRIDE_F + w * 64 + ft;
        const float* b1p = b0p + 8 * STRIDE_F;
        #pragma unroll
        for (int s = 0; s < 8; s++) {
            uint32_t a0 = __float_as_uint(b0p[s * 8]);
            uint32_t a2 = __float_as_uint(b0p[s * 8 + 4]);
            uint32_t a1 = __float_as_uint(b1p[s * 8]);
            uint32_t a3 = __float_as_uint(b1p[s * 8 + 4]);
            MMA_TF32(d1, a0, a1, a2, a3, a0, a2);   // B = rows 0..7
            MMA_TF32(d2, a0, a1, a2, a3, a1, a3);   // B = rows 8..15
        }
        __syncthreads();                          // all warps done with buffer b
        if (i + 2 < n && tid == 0) stage(t_lo + i + 2, b);
    }
    flush_identity(cur_id);
}

extern "C" void kernel_launch(void* const* d_in, const int* in_sizes, int n_in,
                              void* d_out, int out_size)
{
    const float* x = (const float*)d_in[0];
    float* out = (float*)d_out;

    cudaMemsetAsync(out, 0, sizeof(float), 0);

    static bool attr_set = false;
    if (!attr_set) {
        cudaFuncSetAttribute(wloss_kernel,
                             cudaFuncAttributeMaxDynamicSharedMemorySize,
                             SMEM_BYTES);
        attr_set = true;
    }

    wloss_kernel<<<GRID, THREADS, SMEM_BYTES>>>(x, out);
}